// round 16
// baseline (speedup 1.0000x reference)
#include <cuda_runtime.h>
#include <cuda_fp16.h>
#include <math.h>
#include <stdint.h>

#define NB   32
#define TT   128
#define BT   4096
#define CIN  4096
#define NF   64
#define GOUT 4096

// ---------------- scratch (device globals; no allocation allowed) ----------
__device__ float q_buf[(size_t)NB * TT * NF];
__device__ float k_buf[(size_t)NB * TT * NF];
__device__ __align__(1024) __half x1f[(size_t)BT * CIN];
__device__ __align__(1024) __half x2f[(size_t)BT * CIN];
__device__ __align__(1024) __half wgf[(size_t)GOUT * CIN];
__device__ __align__(1024) __half w1f[(size_t)NF * CIN];
__device__ __align__(1024) __half w2f[(size_t)NF * CIN];
__device__ __align__(1024) __half act_f[(size_t)NB * TT * TT];

// ---------------- small PTX helpers ----------------------------------------
__device__ __forceinline__ uint32_t smem_u32(const void* p) {
    uint32_t a;
    asm("{ .reg .u64 t; cvta.to.shared.u64 t, %1; cvt.u32.u64 %0, t; }" : "=r"(a) : "l"(p));
    return a;
}
__device__ __forceinline__ void cp_async16(uint32_t dst, const void* src) {
    asm volatile("cp.async.cg.shared.global [%0], [%1], 16;" :: "r"(dst), "l"(src) : "memory");
}
__device__ __forceinline__ void ldm_x4(uint32_t& r0, uint32_t& r1, uint32_t& r2, uint32_t& r3,
                                       uint32_t addr) {
    asm volatile("ldmatrix.sync.aligned.m8n8.x4.shared.b16 {%0,%1,%2,%3}, [%4];"
                 : "=r"(r0), "=r"(r1), "=r"(r2), "=r"(r3) : "r"(addr));
}
__device__ __forceinline__ void ldm_x4_t(uint32_t& r0, uint32_t& r1, uint32_t& r2, uint32_t& r3,
                                         uint32_t addr) {
    asm volatile("ldmatrix.sync.aligned.m8n8.x4.trans.shared.b16 {%0,%1,%2,%3}, [%4];"
                 : "=r"(r0), "=r"(r1), "=r"(r2), "=r"(r3) : "r"(addr));
}
__device__ __forceinline__ void mma16816h(float* c, const uint32_t* a, const uint32_t* b) {
    asm volatile("mma.sync.aligned.m16n8k16.row.col.f32.f16.f16.f32 "
                 "{%0,%1,%2,%3}, {%4,%5,%6,%7}, {%8,%9}, {%0,%1,%2,%3};"
                 : "+f"(c[0]), "+f"(c[1]), "+f"(c[2]), "+f"(c[3])
                 : "r"(a[0]), "r"(a[1]), "r"(a[2]), "r"(a[3]), "r"(b[0]), "r"(b[1]));
}
#define SWZ(o) ((o) ^ (((o) >> 3) & 0x70))

// ---------------- single fused conversion kernel (2x float4 ILP) -------------
#define BIGB2 8192
#define SMLB2 128
#define BIGH  2097152      // half of BT*CIN/4
#define SMLH  32768        // half of NF*CIN/4
#define CONV_BLOCKS (3 * BIGB2 + 2 * SMLB2)

__global__ void __launch_bounds__(256)
conv_all(const float* __restrict__ x1, const float* __restrict__ x2,
         const float* __restrict__ wg, const float* __restrict__ w1,
         const float* __restrict__ w2,
         __half* __restrict__ ox1, __half* __restrict__ ox2,
         __half* __restrict__ owg, __half* __restrict__ ow1,
         __half* __restrict__ ow2)
{
    int bid = blockIdx.x;
    const float* src;
    __half* dst;
    int i0, half;
    if (bid < BIGB2)            { src = x1; dst = ox1; i0 = bid * 256 + threadIdx.x; half = BIGH; }
    else if (bid < 2 * BIGB2)   { src = x2; dst = ox2; i0 = (bid - BIGB2) * 256 + threadIdx.x; half = BIGH; }
    else if (bid < 3 * BIGB2)   { src = wg; dst = owg; i0 = (bid - 2*BIGB2) * 256 + threadIdx.x; half = BIGH; }
    else if (bid < 3*BIGB2 + SMLB2) { src = w1; dst = ow1; i0 = (bid - 3*BIGB2) * 256 + threadIdx.x; half = SMLH; }
    else                        { src = w2; dst = ow2; i0 = (bid - 3*BIGB2 - SMLB2) * 256 + threadIdx.x; half = SMLH; }
    int i1 = i0 + half;
    float4 v0 = ((const float4*)src)[i0];
    float4 v1 = ((const float4*)src)[i1];
    ((__half2*)dst)[2*i0]   = __half2(__float2half_rn(v0.x), __float2half_rn(v0.y));
    ((__half2*)dst)[2*i0+1] = __half2(__float2half_rn(v0.z), __float2half_rn(v0.w));
    ((__half2*)dst)[2*i1]   = __half2(__float2half_rn(v1.x), __float2half_rn(v1.y));
    ((__half2*)dst)[2*i1+1] = __half2(__float2half_rn(v1.z), __float2half_rn(v1.w));
}

// ---------------- fused g + out GEMM, 128x64 tile, up to 3 CTA/SM ------------
// Phase 1: gtile = fp16(x1[b]) @ fp16(wg[bn..bn+64])^T + bg  (K=4096)
// Phase 2: out[b][:, bn:bn+64] = act[b] @ gtile               (K=128)
// 8 warps, warp tile 32x32 (4 m-warps x 2 n-warps).
#define BKC 32
#define NCHUNK (CIN / BKC)
#define ST_A  0
#define ST_B  8192
#define STAGE_B 12288
#define GT_OFF (2 * STAGE_B)            // 24576, 128B swizzled rows (16KB)
#define AT_OFF (GT_OFF + 16384)         // 40960, 256B swizzled rows (32KB)
#define SMEM_G (512 + AT_OFF + 32768)   // 74240 B/CTA

__global__ void __launch_bounds__(256, 3)
g_out_gemm(const __half* __restrict__ A, const __half* __restrict__ B,
           const float* __restrict__ bias, const __half* __restrict__ Act,
           float* __restrict__ Out)
{
    extern __shared__ char smem_raw[];
    const uint32_t base = (smem_u32(smem_raw) + 511u) & ~511u;

    const int tid  = threadIdx.x;
    const int wid  = tid >> 5;
    const int lane = tid & 31;
    const int b  = blockIdx.y;
    const int bm = b * 128;
    const int bn = blockIdx.x * 64;
    const int wm = (wid >> 1) * 32;     // {0,32,64,96}
    const int wn = (wid & 1) * 32;      // {0,32}

    auto load_chunk = [&](int c, uint32_t st) {
        const int k0 = c * BKC;
        #pragma unroll
        for (int i = 0; i < 2; i++) {               // A: 512 units (128 rows x 64B)
            int u   = tid + i * 256;
            int row = u >> 2;
            int cu  = u & 3;
            uint32_t so = SWZ((uint32_t)(row * 64 + cu * 16));
            cp_async16(st + ST_A + so, A + (size_t)(bm + row) * CIN + k0 + cu * 8);
        }
        {                                            // B: 256 units (64 rows x 64B)
            int row = tid >> 2;
            int cu  = tid & 3;
            uint32_t so = SWZ((uint32_t)(row * 64 + cu * 16));
            cp_async16(st + ST_B + so, B + (size_t)(bn + row) * CIN + k0 + cu * 8);
        }
    };

    // prologue: chunk 0 + act[b] (scores ran earlier) in group 0; chunk 1 group 1
    load_chunk(0, base);
    #pragma unroll
    for (int i = 0; i < 8; i++) {
        int u   = tid + i * 256;
        int row = u >> 4;
        int cu  = u & 15;
        cp_async16(base + AT_OFF + SWZ((uint32_t)(row * 256 + cu * 16)),
                   Act + ((size_t)b * TT + row) * TT + cu * 8);
    }
    asm volatile("cp.async.commit_group;" ::: "memory");
    load_chunk(1, base + STAGE_B);
    asm volatile("cp.async.commit_group;" ::: "memory");

    float acc[2][4][4];
    #pragma unroll
    for (int i = 0; i < 2; i++)
        #pragma unroll
        for (int j = 0; j < 4; j++)
            #pragma unroll
            for (int r = 0; r < 4; r++) acc[i][j][r] = 0.f;

    const int sub = lane >> 3;
    const int lr  = lane & 7;
    const int a_row_off = (sub & 1) * 8 + lr;
    const int a_cu_off  = (sub >> 1);
    const int b_row_off = (sub >> 1) * 8 + lr;   // phase-1 non-trans B
    const int b_cu_off  = (sub & 1);
    const int bt_row_off = (sub & 1) * 8 + lr;   // phase-2 trans B
    const int bt_cu_off  = (sub >> 1);

    for (int c = 0; c < NCHUNK; c++) {
        const uint32_t st = base + (uint32_t)(c & 1) * STAGE_B;
        if (c < NCHUNK - 1) asm volatile("cp.async.wait_group 1;" ::: "memory");
        else                asm volatile("cp.async.wait_group 0;" ::: "memory");
        __syncthreads();

        #pragma unroll
        for (int ks = 0; ks < 2; ks++) {
            uint32_t aF[2][4], bF[4][2];
            #pragma unroll
            for (int mt = 0; mt < 2; mt++) {
                uint32_t off = SWZ((uint32_t)((wm + mt*16 + a_row_off) * 64
                                              + (ks*2 + a_cu_off) * 16));
                ldm_x4(aF[mt][0], aF[mt][1], aF[mt][2], aF[mt][3], st + ST_A + off);
            }
            #pragma unroll
            for (int np = 0; np < 2; np++) {
                uint32_t off = SWZ((uint32_t)((wn + np*16 + b_row_off) * 64
                                              + (ks*2 + b_cu_off) * 16));
                ldm_x4(bF[2*np][0], bF[2*np][1], bF[2*np+1][0], bF[2*np+1][1],
                       st + ST_B + off);
            }
            #pragma unroll
            for (int mt = 0; mt < 2; mt++)
                #pragma unroll
                for (int nt = 0; nt < 4; nt++)
                    mma16816h(acc[mt][nt], aF[mt], bF[nt]);
        }
        __syncthreads();
        if (c + 2 < NCHUNK) {
            load_chunk(c + 2, st);
            asm volatile("cp.async.commit_group;" ::: "memory");
        }
    }

    // ---- phase 1 epilogue: gtile (+bias) -> fp16 smem, 128B swizzled rows ----
    const int q  = lane >> 2;
    const int i2 = (lane & 3) * 2;
    char* smem_gen = smem_raw + (base - smem_u32(smem_raw));
    #pragma unroll
    for (int mt = 0; mt < 2; mt++) {
        #pragma unroll
        for (int nt = 0; nt < 4; nt++) {
            int s0 = wm + mt*16 + q;          // g s-row (0..127)
            int n0 = wn + nt*8 + i2;          // local col (0..63)
            float2 bv = *(const float2*)(bias + bn + n0);
            __half2 o0 = __half2(__float2half_rn(acc[mt][nt][0] + bv.x),
                                 __float2half_rn(acc[mt][nt][1] + bv.y));
            __half2 o1 = __half2(__float2half_rn(acc[mt][nt][2] + bv.x),
                                 __float2half_rn(acc[mt][nt][3] + bv.y));
            *(__half2*)(smem_gen + GT_OFF + SWZ((uint32_t)(s0 * 128 + n0 * 2)))       = o0;
            *(__half2*)(smem_gen + GT_OFF + SWZ((uint32_t)((s0 + 8) * 128 + n0 * 2))) = o1;
        }
    }
    __syncthreads();

    // ---- phase 2: out tile = act[b] @ gtile, K = 128 ----
    #pragma unroll
    for (int i = 0; i < 2; i++)
        #pragma unroll
        for (int j = 0; j < 4; j++)
            #pragma unroll
            for (int r = 0; r < 4; r++) acc[i][j][r] = 0.f;

    #pragma unroll
    for (int ks = 0; ks < 8; ks++) {
        uint32_t aF[2][4], bF[4][2];
        #pragma unroll
        for (int mt = 0; mt < 2; mt++) {
            uint32_t off = SWZ((uint32_t)((wm + mt*16 + a_row_off) * 256
                                          + ks*32 + a_cu_off * 16));
            ldm_x4(aF[mt][0], aF[mt][1], aF[mt][2], aF[mt][3], base + AT_OFF + off);
        }
        #pragma unroll
        for (int np = 0; np < 2; np++) {
            int n0 = wn + np*16;
            uint32_t off = SWZ((uint32_t)((ks*16 + bt_row_off) * 128
                                          + n0*2 + bt_cu_off * 16));
            ldm_x4_t(bF[2*np][0], bF[2*np][1], bF[2*np+1][0], bF[2*np+1][1],
                     base + GT_OFF + off);
        }
        #pragma unroll
        for (int mt = 0; mt < 2; mt++)
            #pragma unroll
            for (int nt = 0; nt < 4; nt++)
                mma16816h(acc[mt][nt], aF[mt], bF[nt]);
    }

    #pragma unroll
    for (int mt = 0; mt < 2; mt++) {
        #pragma unroll
        for (int nt = 0; nt < 4; nt++) {
            int t0 = wm + mt*16 + q;
            int n0 = bn + wn + nt*8 + i2;
            float2 o0 = { acc[mt][nt][0], acc[mt][nt][1] };
            float2 o1 = { acc[mt][nt][2], acc[mt][nt][3] };
            *(float2*)(Out + ((size_t)b*TT + t0) * GOUT + n0)     = o0;
            *(float2*)(Out + ((size_t)b*TT + t0 + 8) * GOUT + n0) = o1;
        }
    }
}

// ---------------- q/k GEMM: 64x64 tile, pure fp16 1-term ---------------------
#define QK_BK 64
#define QK_NCH (CIN / QK_BK)
#define QK_A 0
#define QK_B 8192
#define QK_STAGE 16384
#define SMEM_QK (1024 + 2 * QK_STAGE)

__global__ void __launch_bounds__(128, 1)
qk_gemm_f16(const __half* __restrict__ X1, const __half* __restrict__ X2,
            const __half* __restrict__ W1, const __half* __restrict__ W2,
            const float* __restrict__ b1, const float* __restrict__ b2,
            float* __restrict__ Q, float* __restrict__ K)
{
    extern __shared__ char smem_raw[];
    const uint32_t base = (smem_u32(smem_raw) + 1023u) & ~1023u;

    const int sel = blockIdx.y;
    const __half* A = sel ? X2 : X1;
    const __half* B = sel ? W2 : W1;
    const float* bias = sel ? b2 : b1;
    float* C = sel ? K : Q;

    const int tid  = threadIdx.x;
    const int wid  = tid >> 5;
    const int lane = tid & 31;
    const int bm = blockIdx.x * 64;
    const int wm = (wid >> 1) * 32;
    const int wn = (wid & 1) * 32;

    auto load_chunk = [&](int c, uint32_t st) {
        const int k0 = c * QK_BK;
        #pragma unroll
        for (int i = 0; i < 4; i++) {
            int u   = tid + i * 128;
            int row = u >> 3;
            int ku  = u & 7;
            uint32_t so = SWZ((uint32_t)(row * 128 + ku * 16));
            cp_async16(st + QK_A + so, A + (size_t)(bm + row) * CIN + k0 + ku * 8);
            cp_async16(st + QK_B + so, B + (size_t)row * CIN + k0 + ku * 8);
        }
        asm volatile("cp.async.commit_group;" ::: "memory");
    };

    load_chunk(0, base);
    load_chunk(1, base + QK_STAGE);

    float acc[2][4][4];
    #pragma unroll
    for (int i = 0; i < 2; i++)
        #pragma unroll
        for (int j = 0; j < 4; j++)
            #pragma unroll
            for (int r = 0; r < 4; r++) acc[i][j][r] = 0.f;

    const int sub = lane >> 3;
    const int lr  = lane & 7;
    const int a_row_off = (sub & 1) * 8 + lr;
    const int a_cu_off  = (sub >> 1);
    const int b_row_off = (sub >> 1) * 8 + lr;
    const int b_cu_off  = (sub & 1);

    for (int c = 0; c < QK_NCH; c++) {
        const uint32_t st = base + (uint32_t)(c & 1) * QK_STAGE;
        if (c < QK_NCH - 1) asm volatile("cp.async.wait_group 1;" ::: "memory");
        else                asm volatile("cp.async.wait_group 0;" ::: "memory");
        __syncthreads();

        #pragma unroll
        for (int ks = 0; ks < 4; ks++) {
            uint32_t aF[2][4], bF[4][2];
            #pragma unroll
            for (int mt = 0; mt < 2; mt++) {
                uint32_t off = SWZ((uint32_t)((wm + mt*16 + a_row_off) * 128
                                              + (ks*2 + a_cu_off) * 16));
                ldm_x4(aF[mt][0], aF[mt][1], aF[mt][2], aF[mt][3], st + QK_A + off);
            }
            #pragma unroll
            for (int np = 0; np < 2; np++) {
                uint32_t off = SWZ((uint32_t)((wn + np*16 + b_row_off) * 128
                                              + (ks*2 + b_cu_off) * 16));
                ldm_x4(bF[2*np][0], bF[2*np][1], bF[2*np+1][0], bF[2*np+1][1],
                       st + QK_B + off);
            }
            #pragma unroll
            for (int mt = 0; mt < 2; mt++)
                #pragma unroll
                for (int nt = 0; nt < 4; nt++)
                    mma16816h(acc[mt][nt], aF[mt], bF[nt]);
        }
        __syncthreads();
        if (c + 2 < QK_NCH) load_chunk(c + 2, st);
    }

    const int q = lane >> 2;
    const int i2 = (lane & 3) * 2;
    #pragma unroll
    for (int mt = 0; mt < 2; mt++) {
        #pragma unroll
        for (int nt = 0; nt < 4; nt++) {
            int m0 = bm + wm + mt*16 + q;
            int n0 = wn + nt*8 + i2;
            float2 bv = *(const float2*)(bias + n0);
            float2 o0 = { acc[mt][nt][0] + bv.x, acc[mt][nt][1] + bv.y };
            float2 o1 = { acc[mt][nt][2] + bv.x, acc[mt][nt][3] + bv.y };
            *(float2*)(C + (size_t)m0 * NF + n0)     = o0;
            *(float2*)(C + (size_t)(m0+8) * NF + n0) = o1;
        }
    }
}

// ---------------- scores + fused activation -> act fp16 ----------------------
__global__ void __launch_bounds__(512)
scores_act_kernel(const float* __restrict__ actw,
                  const float* __restrict__ qb,
                  const float* __restrict__ kb,
                  __half* __restrict__ af)
{
    const int b  = blockIdx.x;
    const int s  = blockIdx.y * 32 + (threadIdx.x >> 4);
    const int tp = threadIdx.x & 15;

    __shared__ float qs[TT * NF];
    for (int idx = threadIdx.x; idx < TT*NF; idx += 512)
        qs[idx] = qb[(size_t)b*TT*NF + idx];

    float kr[NF];
    #pragma unroll
    for (int f = 0; f < NF; ++f) kr[f] = kb[((size_t)b*TT + s)*NF + f];
    __syncthreads();

    float col[8];
    float mx = -1e30f;
    #pragma unroll
    for (int i = 0; i < 8; ++i) {
        const float* qrow = qs + (tp*8 + i)*NF;
        float v = 0.f;
        #pragma unroll
        for (int f = 0; f < NF; ++f) v = fmaf(qrow[f], kr[f], v);
        col[i] = v;
        mx = fmaxf(mx, v);
    }
    #pragma unroll
    for (int d = 1; d < 16; d <<= 1)
        mx = fmaxf(mx, __shfl_xor_sync(0xffffffffu, mx, d));
    float sum = 0.f;
    #pragma unroll
    for (int i = 0; i < 8; ++i) sum += expf(col[i] - mx);
    #pragma unroll
    for (int d = 1; d < 16; d <<= 1)
        sum += __shfl_xor_sync(0xffffffffu, sum, d);
    const float inv = 1.f / sum;
    const float w0 = actw[0], w1 = actw[1], w2 = actw[2];
    __half* pf = af + (size_t)b*TT*TT + s;
    #pragma unroll
    for (int i = 0; i < 8; ++i) {
        int t = tp*8 + i;
        float v = col[i];
        float a = w0 * fmaxf(v, 0.f)
                + w1 * (1.f / (1.f + expf(-v)))
                + w2 * (expf(v - mx) * inv);
        pf[t*TT] = __float2half_rn(a);
    }
}

// ---------------------------------------------------------------------------
extern "C" void kernel_launch(void* const* d_in, const int* in_sizes, int n_in,
                              void* d_out, int out_size)
{
    const float* x1   = (const float*)d_in[0];
    const float* x2   = (const float*)d_in[1];
    const float* actw = (const float*)d_in[2];
    const float* w1   = (const float*)d_in[3];
    const float* b1   = (const float*)d_in[4];
    const float* w2   = (const float*)d_in[5];
    const float* b2   = (const float*)d_in[6];
    const float* wg   = (const float*)d_in[7];
    const float* bg   = (const float*)d_in[8];
    float* out = (float*)d_out;

    float *qp, *kp;
    __half *x1fp, *x2fp, *wgfp, *w1fp, *w2fp, *actfp;
    cudaGetSymbolAddress((void**)&qp, q_buf);
    cudaGetSymbolAddress((void**)&kp, k_buf);
    cudaGetSymbolAddress((void**)&x1fp, x1f);
    cudaGetSymbolAddress((void**)&x2fp, x2f);
    cudaGetSymbolAddress((void**)&wgfp, wgf);
    cudaGetSymbolAddress((void**)&w1fp, w1f);
    cudaGetSymbolAddress((void**)&w2fp, w2f);
    cudaGetSymbolAddress((void**)&actfp, act_f);

    cudaFuncSetAttribute(g_out_gemm, cudaFuncAttributeMaxDynamicSharedMemorySize, SMEM_G);
    cudaFuncSetAttribute(qk_gemm_f16, cudaFuncAttributeMaxDynamicSharedMemorySize, SMEM_QK);

    // all conversions in ONE launch (2x float4 per thread)
    conv_all<<<CONV_BLOCKS, 256>>>(x1, x2, wg, w1, w2,
                                   x1fp, x2fp, wgfp, w1fp, w2fp);

    // q and k projections (pure fp16 1-term)
    qk_gemm_f16<<<dim3(BT/64, 2), 128, SMEM_QK>>>(x1fp, x2fp, w1fp, w2fp,
                                                  b1, b2, qp, kp);

    // scores -> fused activation -> act fp16 (must precede fused g+out)
    scores_act_kernel<<<dim3(NB, 4), 512>>>(actw, qp, kp, actfp);

    // fused: g tile 128x64 (fp16) -> epilogue out tile = act[b] @ gtile
    g_out_gemm<<<dim3(GOUT/64, NB), 256, SMEM_G>>>(x1fp, wgfp, bg, actfp, out);
}

// round 17
// speedup vs baseline: 1.1325x; 1.1325x over previous
#include <cuda_runtime.h>
#include <cuda_fp16.h>
#include <math.h>
#include <stdint.h>

#define NB   32
#define TT   128
#define BT   4096
#define CIN  4096
#define NF   64
#define GOUT 4096

// ---------------- scratch (device globals; no allocation allowed) ----------
__device__ float q_buf[(size_t)NB * TT * NF];
__device__ float k_buf[(size_t)NB * TT * NF];
__device__ __align__(1024) __half x1f[(size_t)BT * CIN];
__device__ __align__(1024) __half x2f[(size_t)BT * CIN];
__device__ __align__(1024) __half wgf[(size_t)GOUT * CIN];
__device__ __align__(1024) __half w1f[(size_t)NF * CIN];
__device__ __align__(1024) __half w2f[(size_t)NF * CIN];
__device__ __align__(1024) __half act_f[(size_t)NB * TT * TT];

// ---------------- small PTX helpers ----------------------------------------
__device__ __forceinline__ uint32_t smem_u32(const void* p) {
    uint32_t a;
    asm("{ .reg .u64 t; cvta.to.shared.u64 t, %1; cvt.u32.u64 %0, t; }" : "=r"(a) : "l"(p));
    return a;
}
__device__ __forceinline__ void cp_async16(uint32_t dst, const void* src) {
    asm volatile("cp.async.cg.shared.global [%0], [%1], 16;" :: "r"(dst), "l"(src) : "memory");
}
__device__ __forceinline__ void ldm_x4(uint32_t& r0, uint32_t& r1, uint32_t& r2, uint32_t& r3,
                                       uint32_t addr) {
    asm volatile("ldmatrix.sync.aligned.m8n8.x4.shared.b16 {%0,%1,%2,%3}, [%4];"
                 : "=r"(r0), "=r"(r1), "=r"(r2), "=r"(r3) : "r"(addr));
}
__device__ __forceinline__ void ldm_x4_t(uint32_t& r0, uint32_t& r1, uint32_t& r2, uint32_t& r3,
                                         uint32_t addr) {
    asm volatile("ldmatrix.sync.aligned.m8n8.x4.trans.shared.b16 {%0,%1,%2,%3}, [%4];"
                 : "=r"(r0), "=r"(r1), "=r"(r2), "=r"(r3) : "r"(addr));
}
__device__ __forceinline__ void mma16816h(float* c, const uint32_t* a, const uint32_t* b) {
    asm volatile("mma.sync.aligned.m16n8k16.row.col.f32.f16.f16.f32 "
                 "{%0,%1,%2,%3}, {%4,%5,%6,%7}, {%8,%9}, {%0,%1,%2,%3};"
                 : "+f"(c[0]), "+f"(c[1]), "+f"(c[2]), "+f"(c[3])
                 : "r"(a[0]), "r"(a[1]), "r"(a[2]), "r"(a[3]), "r"(b[0]), "r"(b[1]));
}
#define SWZ(o) ((o) ^ (((o) >> 3) & 0x70))

// ---------------- single fused conversion kernel (2x float4 ILP) -------------
#define BIGB2 8192
#define SMLB2 128
#define BIGH  2097152      // half of BT*CIN/4
#define SMLH  32768        // half of NF*CIN/4
#define CONV_BLOCKS (3 * BIGB2 + 2 * SMLB2)

__global__ void __launch_bounds__(256)
conv_all(const float* __restrict__ x1, const float* __restrict__ x2,
         const float* __restrict__ wg, const float* __restrict__ w1,
         const float* __restrict__ w2,
         __half* __restrict__ ox1, __half* __restrict__ ox2,
         __half* __restrict__ owg, __half* __restrict__ ow1,
         __half* __restrict__ ow2)
{
    int bid = blockIdx.x;
    const float* src;
    __half* dst;
    int i0, half;
    if (bid < BIGB2)            { src = x1; dst = ox1; i0 = bid * 256 + threadIdx.x; half = BIGH; }
    else if (bid < 2 * BIGB2)   { src = x2; dst = ox2; i0 = (bid - BIGB2) * 256 + threadIdx.x; half = BIGH; }
    else if (bid < 3 * BIGB2)   { src = wg; dst = owg; i0 = (bid - 2*BIGB2) * 256 + threadIdx.x; half = BIGH; }
    else if (bid < 3*BIGB2 + SMLB2) { src = w1; dst = ow1; i0 = (bid - 3*BIGB2) * 256 + threadIdx.x; half = SMLH; }
    else                        { src = w2; dst = ow2; i0 = (bid - 3*BIGB2 - SMLB2) * 256 + threadIdx.x; half = SMLH; }
    int i1 = i0 + half;
    float4 v0 = ((const float4*)src)[i0];
    float4 v1 = ((const float4*)src)[i1];
    ((__half2*)dst)[2*i0]   = __half2(__float2half_rn(v0.x), __float2half_rn(v0.y));
    ((__half2*)dst)[2*i0+1] = __half2(__float2half_rn(v0.z), __float2half_rn(v0.w));
    ((__half2*)dst)[2*i1]   = __half2(__float2half_rn(v1.x), __float2half_rn(v1.y));
    ((__half2*)dst)[2*i1+1] = __half2(__float2half_rn(v1.z), __float2half_rn(v1.w));
}

// ---------------- fused g + out GEMM, 128x128 tile, 2 CTA/SM (optimal) -------
#define BKC 32
#define NCHUNK (CIN / BKC)
#define ST_A  0
#define ST_B  8192
#define STAGE_B 16384
#define OROW 272
#define GT_OFF 32768
#define AT_OFF (32768 + 128 * OROW)
#define SMEM_G (1024 + 32768 + 2 * 128 * OROW)

__global__ void __launch_bounds__(256, 2)
g_out_gemm(const __half* __restrict__ A, const __half* __restrict__ B,
           const float* __restrict__ bias, const __half* __restrict__ Act,
           float* __restrict__ Out)
{
    extern __shared__ char smem_raw[];
    const uint32_t base = (smem_u32(smem_raw) + 1023u) & ~1023u;

    const int tid  = threadIdx.x;
    const int wid  = tid >> 5;
    const int lane = tid & 31;
    const int b  = blockIdx.y;
    const int bm = b * 128;
    const int bn = blockIdx.x * 128;
    const int wm = (wid >> 2) * 64;
    const int wn = (wid & 3) * 32;

    auto load_chunk = [&](int c, uint32_t st) {
        const int k0 = c * BKC;
        #pragma unroll
        for (int i = 0; i < 2; i++) {
            int u   = tid + i * 256;
            int row = u >> 2;
            int cu  = u & 3;
            uint32_t so = SWZ((uint32_t)(row * 64 + cu * 16));
            cp_async16(st + ST_A + so, A + (size_t)(bm + row) * CIN + k0 + cu * 8);
            cp_async16(st + ST_B + so, B + (size_t)(bn + row) * CIN + k0 + cu * 8);
        }
    };

    load_chunk(0, base);
    #pragma unroll
    for (int i = 0; i < 8; i++) {
        int u   = tid + i * 256;
        int row = u >> 4;
        int cu  = u & 15;
        cp_async16(base + AT_OFF + (uint32_t)(row * OROW + cu * 16),
                   Act + ((size_t)b * TT + row) * TT + cu * 8);
    }
    asm volatile("cp.async.commit_group;" ::: "memory");
    load_chunk(1, base + STAGE_B);
    asm volatile("cp.async.commit_group;" ::: "memory");

    float acc[4][4][4];
    #pragma unroll
    for (int i = 0; i < 4; i++)
        #pragma unroll
        for (int j = 0; j < 4; j++)
            #pragma unroll
            for (int r = 0; r < 4; r++) acc[i][j][r] = 0.f;

    const int sub = lane >> 3;
    const int lr  = lane & 7;
    const int a_row_off = (sub & 1) * 8 + lr;
    const int a_cu_off  = (sub >> 1);
    const int b_row_off = (sub >> 1) * 8 + lr;
    const int b_cu_off  = (sub & 1);
    const int bt_row_off = (sub & 1) * 8 + lr;
    const int bt_cu_off  = (sub >> 1);

    for (int c = 0; c < NCHUNK; c++) {
        const uint32_t st = base + (uint32_t)(c & 1) * STAGE_B;
        if (c < NCHUNK - 1) asm volatile("cp.async.wait_group 1;" ::: "memory");
        else                asm volatile("cp.async.wait_group 0;" ::: "memory");
        __syncthreads();

        #pragma unroll
        for (int ks = 0; ks < 2; ks++) {
            uint32_t aF[4][4], bF[4][2];
            #pragma unroll
            for (int mt = 0; mt < 4; mt++) {
                uint32_t off = SWZ((uint32_t)((wm + mt*16 + a_row_off) * 64
                                              + (ks*2 + a_cu_off) * 16));
                ldm_x4(aF[mt][0], aF[mt][1], aF[mt][2], aF[mt][3], st + ST_A + off);
            }
            #pragma unroll
            for (int np = 0; np < 2; np++) {
                uint32_t off = SWZ((uint32_t)((wn + np*16 + b_row_off) * 64
                                              + (ks*2 + b_cu_off) * 16));
                ldm_x4(bF[2*np][0], bF[2*np][1], bF[2*np+1][0], bF[2*np+1][1],
                       st + ST_B + off);
            }
            #pragma unroll
            for (int mt = 0; mt < 4; mt++)
                #pragma unroll
                for (int nt = 0; nt < 4; nt++)
                    mma16816h(acc[mt][nt], aF[mt], bF[nt]);
        }
        __syncthreads();
        if (c + 2 < NCHUNK) {
            load_chunk(c + 2, st);
            asm volatile("cp.async.commit_group;" ::: "memory");
        }
    }

    // ---- phase 1 epilogue: gtile (+bias) -> fp16 smem [s][n'] 272B rows ----
    const int q  = lane >> 2;
    const int i2 = (lane & 3) * 2;
    char* smem_gen = smem_raw + (base - smem_u32(smem_raw));
    #pragma unroll
    for (int mt = 0; mt < 4; mt++) {
        #pragma unroll
        for (int nt = 0; nt < 4; nt++) {
            int s0 = wm + mt*16 + q;
            int n0 = wn + nt*8 + i2;
            float2 bv = *(const float2*)(bias + bn + n0);
            __half2 o0 = __half2(__float2half_rn(acc[mt][nt][0] + bv.x),
                                 __float2half_rn(acc[mt][nt][1] + bv.y));
            __half2 o1 = __half2(__float2half_rn(acc[mt][nt][2] + bv.x),
                                 __float2half_rn(acc[mt][nt][3] + bv.y));
            *(__half2*)(smem_gen + GT_OFF + s0 * OROW + n0 * 2)       = o0;
            *(__half2*)(smem_gen + GT_OFF + (s0 + 8) * OROW + n0 * 2) = o1;
        }
    }
    __syncthreads();

    // ---- phase 2: out tile = act[b] @ gtile, K = 128 ----
    #pragma unroll
    for (int i = 0; i < 4; i++)
        #pragma unroll
        for (int j = 0; j < 4; j++)
            #pragma unroll
            for (int r = 0; r < 4; r++) acc[i][j][r] = 0.f;

    #pragma unroll
    for (int ks = 0; ks < 8; ks++) {
        uint32_t aF[4][4], bF[4][2];
        #pragma unroll
        for (int mt = 0; mt < 4; mt++) {
            uint32_t off = (uint32_t)((wm + mt*16 + a_row_off) * OROW
                                      + ks*32 + a_cu_off * 16);
            ldm_x4(aF[mt][0], aF[mt][1], aF[mt][2], aF[mt][3], base + AT_OFF + off);
        }
        #pragma unroll
        for (int np = 0; np < 2; np++) {
            int n0 = wn + np*16;
            uint32_t off = (uint32_t)((ks*16 + bt_row_off) * OROW
                                      + n0*2 + bt_cu_off * 16);
            ldm_x4_t(bF[2*np][0], bF[2*np][1], bF[2*np+1][0], bF[2*np+1][1],
                     base + GT_OFF + off);
        }
        #pragma unroll
        for (int mt = 0; mt < 4; mt++)
            #pragma unroll
            for (int nt = 0; nt < 4; nt++)
                mma16816h(acc[mt][nt], aF[mt], bF[nt]);
    }

    #pragma unroll
    for (int mt = 0; mt < 4; mt++) {
        #pragma unroll
        for (int nt = 0; nt < 4; nt++) {
            int t0 = wm + mt*16 + q;
            int n0 = bn + wn + nt*8 + i2;
            float2 o0 = { acc[mt][nt][0], acc[mt][nt][1] };
            float2 o1 = { acc[mt][nt][2], acc[mt][nt][3] };
            *(float2*)(Out + ((size_t)b*TT + t0) * GOUT + n0)     = o0;
            *(float2*)(Out + ((size_t)b*TT + t0 + 8) * GOUT + n0) = o1;
        }
    }
}

// ---------------- q/k GEMM: 64x64 tile, pure fp16 1-term ---------------------
#define QK_BK 64
#define QK_NCH (CIN / QK_BK)
#define QK_A 0
#define QK_B 8192
#define QK_STAGE 16384
#define SMEM_QK (1024 + 2 * QK_STAGE)

__global__ void __launch_bounds__(128, 1)
qk_gemm_f16(const __half* __restrict__ X1, const __half* __restrict__ X2,
            const __half* __restrict__ W1, const __half* __restrict__ W2,
            const float* __restrict__ b1, const float* __restrict__ b2,
            float* __restrict__ Q, float* __restrict__ K)
{
    extern __shared__ char smem_raw[];
    const uint32_t base = (smem_u32(smem_raw) + 1023u) & ~1023u;

    const int sel = blockIdx.y;
    const __half* A = sel ? X2 : X1;
    const __half* B = sel ? W2 : W1;
    const float* bias = sel ? b2 : b1;
    float* C = sel ? K : Q;

    const int tid  = threadIdx.x;
    const int wid  = tid >> 5;
    const int lane = tid & 31;
    const int bm = blockIdx.x * 64;
    const int wm = (wid >> 1) * 32;
    const int wn = (wid & 1) * 32;

    auto load_chunk = [&](int c, uint32_t st) {
        const int k0 = c * QK_BK;
        #pragma unroll
        for (int i = 0; i < 4; i++) {
            int u   = tid + i * 128;
            int row = u >> 3;
            int ku  = u & 7;
            uint32_t so = SWZ((uint32_t)(row * 128 + ku * 16));
            cp_async16(st + QK_A + so, A + (size_t)(bm + row) * CIN + k0 + ku * 8);
            cp_async16(st + QK_B + so, B + (size_t)row * CIN + k0 + ku * 8);
        }
        asm volatile("cp.async.commit_group;" ::: "memory");
    };

    load_chunk(0, base);
    load_chunk(1, base + QK_STAGE);

    float acc[2][4][4];
    #pragma unroll
    for (int i = 0; i < 2; i++)
        #pragma unroll
        for (int j = 0; j < 4; j++)
            #pragma unroll
            for (int r = 0; r < 4; r++) acc[i][j][r] = 0.f;

    const int sub = lane >> 3;
    const int lr  = lane & 7;
    const int a_row_off = (sub & 1) * 8 + lr;
    const int a_cu_off  = (sub >> 1);
    const int b_row_off = (sub >> 1) * 8 + lr;
    const int b_cu_off  = (sub & 1);

    for (int c = 0; c < QK_NCH; c++) {
        const uint32_t st = base + (uint32_t)(c & 1) * QK_STAGE;
        if (c < QK_NCH - 1) asm volatile("cp.async.wait_group 1;" ::: "memory");
        else                asm volatile("cp.async.wait_group 0;" ::: "memory");
        __syncthreads();

        #pragma unroll
        for (int ks = 0; ks < 4; ks++) {
            uint32_t aF[2][4], bF[4][2];
            #pragma unroll
            for (int mt = 0; mt < 2; mt++) {
                uint32_t off = SWZ((uint32_t)((wm + mt*16 + a_row_off) * 128
                                              + (ks*2 + a_cu_off) * 16));
                ldm_x4(aF[mt][0], aF[mt][1], aF[mt][2], aF[mt][3], st + QK_A + off);
            }
            #pragma unroll
            for (int np = 0; np < 2; np++) {
                uint32_t off = SWZ((uint32_t)((wn + np*16 + b_row_off) * 128
                                              + (ks*2 + b_cu_off) * 16));
                ldm_x4(bF[2*np][0], bF[2*np][1], bF[2*np+1][0], bF[2*np+1][1],
                       st + QK_B + off);
            }
            #pragma unroll
            for (int mt = 0; mt < 2; mt++)
                #pragma unroll
                for (int nt = 0; nt < 4; nt++)
                    mma16816h(acc[mt][nt], aF[mt], bF[nt]);
        }
        __syncthreads();
        if (c + 2 < QK_NCH) load_chunk(c + 2, st);
    }

    const int q = lane >> 2;
    const int i2 = (lane & 3) * 2;
    #pragma unroll
    for (int mt = 0; mt < 2; mt++) {
        #pragma unroll
        for (int nt = 0; nt < 4; nt++) {
            int m0 = bm + wm + mt*16 + q;
            int n0 = wn + nt*8 + i2;
            float2 bv = *(const float2*)(bias + n0);
            float2 o0 = { acc[mt][nt][0] + bv.x, acc[mt][nt][1] + bv.y };
            float2 o1 = { acc[mt][nt][2] + bv.x, acc[mt][nt][3] + bv.y };
            *(float2*)(C + (size_t)m0 * NF + n0)     = o0;
            *(float2*)(C + (size_t)(m0+8) * NF + n0) = o1;
        }
    }
}

// ---------------- scores + fused activation -> act fp16 ----------------------
__global__ void __launch_bounds__(512)
scores_act_kernel(const float* __restrict__ actw,
                  const float* __restrict__ qb,
                  const float* __restrict__ kb,
                  __half* __restrict__ af)
{
    const int b  = blockIdx.x;
    const int s  = blockIdx.y * 32 + (threadIdx.x >> 4);
    const int tp = threadIdx.x & 15;

    __shared__ float qs[TT * NF];
    for (int idx = threadIdx.x; idx < TT*NF; idx += 512)
        qs[idx] = qb[(size_t)b*TT*NF + idx];

    float kr[NF];
    #pragma unroll
    for (int f = 0; f < NF; ++f) kr[f] = kb[((size_t)b*TT + s)*NF + f];
    __syncthreads();

    float col[8];
    float mx = -1e30f;
    #pragma unroll
    for (int i = 0; i < 8; ++i) {
        const float* qrow = qs + (tp*8 + i)*NF;
        float v = 0.f;
        #pragma unroll
        for (int f = 0; f < NF; ++f) v = fmaf(qrow[f], kr[f], v);
        col[i] = v;
        mx = fmaxf(mx, v);
    }
    #pragma unroll
    for (int d = 1; d < 16; d <<= 1)
        mx = fmaxf(mx, __shfl_xor_sync(0xffffffffu, mx, d));
    float sum = 0.f;
    #pragma unroll
    for (int i = 0; i < 8; ++i) sum += expf(col[i] - mx);
    #pragma unroll
    for (int d = 1; d < 16; d <<= 1)
        sum += __shfl_xor_sync(0xffffffffu, sum, d);
    const float inv = 1.f / sum;
    const float w0 = actw[0], w1 = actw[1], w2 = actw[2];
    __half* pf = af + (size_t)b*TT*TT + s;
    #pragma unroll
    for (int i = 0; i < 8; ++i) {
        int t = tp*8 + i;
        float v = col[i];
        float a = w0 * fmaxf(v, 0.f)
                + w1 * (1.f / (1.f + expf(-v)))
                + w2 * (expf(v - mx) * inv);
        pf[t*TT] = __float2half_rn(a);
    }
}

// ---------------------------------------------------------------------------
extern "C" void kernel_launch(void* const* d_in, const int* in_sizes, int n_in,
                              void* d_out, int out_size)
{
    const float* x1   = (const float*)d_in[0];
    const float* x2   = (const float*)d_in[1];
    const float* actw = (const float*)d_in[2];
    const float* w1   = (const float*)d_in[3];
    const float* b1   = (const float*)d_in[4];
    const float* w2   = (const float*)d_in[5];
    const float* b2   = (const float*)d_in[6];
    const float* wg   = (const float*)d_in[7];
    const float* bg   = (const float*)d_in[8];
    float* out = (float*)d_out;

    float *qp, *kp;
    __half *x1fp, *x2fp, *wgfp, *w1fp, *w2fp, *actfp;
    cudaGetSymbolAddress((void**)&qp, q_buf);
    cudaGetSymbolAddress((void**)&kp, k_buf);
    cudaGetSymbolAddress((void**)&x1fp, x1f);
    cudaGetSymbolAddress((void**)&x2fp, x2f);
    cudaGetSymbolAddress((void**)&wgfp, wgf);
    cudaGetSymbolAddress((void**)&w1fp, w1f);
    cudaGetSymbolAddress((void**)&w2fp, w2f);
    cudaGetSymbolAddress((void**)&actfp, act_f);

    cudaFuncSetAttribute(g_out_gemm, cudaFuncAttributeMaxDynamicSharedMemorySize, SMEM_G);
    cudaFuncSetAttribute(qk_gemm_f16, cudaFuncAttributeMaxDynamicSharedMemorySize, SMEM_QK);

    // all conversions in ONE launch (2x float4 per thread)
    conv_all<<<CONV_BLOCKS, 256>>>(x1, x2, wg, w1, w2,
                                   x1fp, x2fp, wgfp, w1fp, w2fp);

    // q and k projections (pure fp16 1-term)
    qk_gemm_f16<<<dim3(BT/64, 2), 128, SMEM_QK>>>(x1fp, x2fp, w1fp, w2fp,
                                                  b1, b2, qp, kp);

    // scores -> fused activation -> act fp16 (must precede fused g+out)
    scores_act_kernel<<<dim3(NB, 4), 512>>>(actw, qp, kp, actfp);

    // fused: g tile 128x128 (fp16) -> epilogue out tile = act[b] @ gtile
    g_out_gemm<<<dim3(GOUT/128, NB), 256, SMEM_G>>>(x1fp, wgfp, bg, actfp, out);
}